// round 1
// baseline (speedup 1.0000x reference)
#include <cuda_runtime.h>
#include <math.h>
#include <stdint.h>

#define BATCH 8
#define CH    384
#define SH    48
#define OUTC  256
#define KD    32
#define RAD   3
#define DIAM  7
#define NTAP  49

// ---------------- scratch (static device globals; no allocation) ----------------
__device__ float g_g1  [BATCH*3*96*96];
__device__ float g_g2  [BATCH*3*192*192];
__device__ float g_p1  [BATCH*96*96*KD];
__device__ float g_p2  [BATCH*192*192*KD];
__device__ float g_c1  [BATCH*96*96*NTAP];
__device__ float g_c2  [BATCH*192*192*NTAP];
__device__ float g_hr1 [(size_t)BATCH*CH*96*96];
__device__ float g_s2  [(size_t)BATCH*CH*96*96];
__device__ float g_hr2 [(size_t)BATCH*CH*192*192];
__device__ float g_s4  [(size_t)BATCH*CH*192*192];
__device__ float g_weff[OUTC*CH];
__device__ float g_beff[OUTC];

__device__ __forceinline__ int refl(int i, int n) {
    if (i < 0) i = -i;
    if (i >= n) i = 2*n - 2 - i;
    return i;
}

// ---------------- W_eff = P + 0.1 P F ; b_eff = pb + 0.1 P fb ----------------
__global__ void weff_kernel(const float* __restrict__ Pw, const float* __restrict__ pb,
                            const float* __restrict__ Fw, const float* __restrict__ fb,
                            float* __restrict__ Weff, float* __restrict__ beff) {
    int idx = blockIdx.x * blockDim.x + threadIdx.x;
    if (idx < OUTC*CH) {
        int o = idx / CH, c = idx % CH;
        float acc = 0.f;
        #pragma unroll 4
        for (int k = 0; k < CH; k++) acc += Pw[o*CH + k] * Fw[k*CH + c];
        Weff[idx] = Pw[o*CH + c] + 0.1f * acc;
    }
    if (idx < OUTC) {
        float a = 0.f;
        for (int k = 0; k < CH; k++) a += Pw[idx*CH + k] * fb[k];
        beff[idx] = pb[idx] + 0.1f * a;
    }
}

// ---------------- adaptive avg pool (exact integer factor) ----------------
__global__ void pool_kernel(const float* __restrict__ g, float* __restrict__ out,
                            int OH, int OW, int F) {
    int idx = blockIdx.x * blockDim.x + threadIdx.x;
    int total = BATCH * 3 * OH * OW;
    if (idx >= total) return;
    int ox = idx % OW; int t = idx / OW;
    int oy = t % OH;   t /= OH;
    int c  = t % 3;    int b = t / 3;
    const float* p = g + (((size_t)(b*3 + c)*768) + (size_t)oy*F)*768 + (size_t)ox*F;
    float s = 0.f;
    for (int i = 0; i < F; i++)
        for (int j = 0; j < F; j++)
            s += p[i*768 + j];
    out[idx] = s / (float)(F*F);
}

// ---------------- range projection MLP: 3 -> 32 (gelu) -> 32, pixel-major out ----------------
__global__ void rproj_kernel(const float* __restrict__ g,
                             const float* __restrict__ w1, const float* __restrict__ b1,
                             const float* __restrict__ w2, const float* __restrict__ b2,
                             float* __restrict__ proj, int GH, int GW) {
    __shared__ float sw1[KD*3], sb1[KD], sw2[KD*KD], sb2[KD];
    int tid = threadIdx.x;
    for (int i = tid; i < KD*3;  i += blockDim.x) sw1[i] = w1[i];
    for (int i = tid; i < KD;    i += blockDim.x) { sb1[i] = b1[i]; sb2[i] = b2[i]; }
    for (int i = tid; i < KD*KD; i += blockDim.x) sw2[i] = w2[i];
    __syncthreads();
    int idx = blockIdx.x * blockDim.x + tid;
    int plane = GH * GW;
    if (idx >= BATCH * plane) return;
    int b = idx / plane, pix = idx % plane;
    float g0 = g[(size_t)(b*3 + 0)*plane + pix];
    float g1v = g[(size_t)(b*3 + 1)*plane + pix];
    float g2v = g[(size_t)(b*3 + 2)*plane + pix];
    float h[KD];
    #pragma unroll
    for (int o = 0; o < KD; o++) {
        float x = sw1[o*3]*g0 + sw1[o*3+1]*g1v + sw1[o*3+2]*g2v + sb1[o];
        float u = 0.7978845608028654f * (x + 0.044715f * x*x*x);
        h[o] = 0.5f * x * (1.f + tanhf(u));
    }
    float* op = proj + (size_t)idx * KD;
    #pragma unroll
    for (int o = 0; o < KD; o++) {
        float s = sb2[o];
        #pragma unroll
        for (int k = 0; k < KD; k++) s += sw2[o*KD + k] * h[k];
        op[o] = s;
    }
}

// ---------------- combined 49-tap kernel: softmax(range) * spatial, normalized ----------------
__global__ void comb_kernel(const float* __restrict__ proj,
                            const float* __restrict__ rt_p, const float* __restrict__ sig_p,
                            float* __restrict__ comb, int GH, int GW) {
    int idx = blockIdx.x * blockDim.x + threadIdx.x;
    int plane = GH * GW;
    if (idx >= BATCH * plane) return;
    int b = idx / plane, pix = idx % plane;
    int y = pix / GW, x = pix % GW;
    const float4* base4 = (const float4*)(proj + (size_t)b*plane*KD);

    float4 cv[KD/4];
    const float4* cp = base4 + (size_t)pix * (KD/4);
    #pragma unroll
    for (int q = 0; q < KD/4; q++) cv[q] = cp[q];

    float temp = expf(rt_p[0]);
    temp = fminf(fmaxf(temp, 1e-4f), 1e4f);
    float sig = sig_p[0];
    float inv2s2 = 1.f / (2.f * sig * sig);

    int ys[DIAM], xs[DIAM];
    #pragma unroll
    for (int i = 0; i < DIAM; i++) { ys[i] = refl(y + i - RAD, GH); xs[i] = refl(x + i - RAD, GW); }

    float l[NTAP];
    float m = -1e30f;
    #pragma unroll
    for (int i = 0; i < DIAM; i++) {
        #pragma unroll
        for (int j = 0; j < DIAM; j++) {
            const float4* np = base4 + (size_t)(ys[i]*GW + xs[j]) * (KD/4);
            float d = 0.f;
            #pragma unroll
            for (int q = 0; q < KD/4; q++) {
                float4 nv = __ldg(&np[q]);
                d += cv[q].x*nv.x + cv[q].y*nv.y + cv[q].z*nv.z + cv[q].w*nv.w;
            }
            d *= temp;
            l[i*DIAM + j] = d;
            m = fmaxf(m, d);
        }
    }
    float Z = 0.f;
    #pragma unroll
    for (int p = 0; p < NTAP; p++) { l[p] = expf(l[p] - m); Z += l[p]; }
    float invZ = 1.f / Z;
    float S = 0.f;
    #pragma unroll
    for (int p = 0; p < NTAP; p++) {
        int i = p / DIAM, j = p % DIAM;
        float dy = (i - 3) * (1.f/3.f), dx = (j - 3) * (1.f/3.f);
        float sp = expf(-(dx*dx + dy*dy) * inv2s2);
        l[p] = (l[p] * invZ) * sp;
        S += l[p];
    }
    S = fmaxf(S, 1e-7f);
    float invS = 1.f / S;
    float* op = comb + (size_t)idx * NTAP;
    #pragma unroll
    for (int p = 0; p < NTAP; p++) op[p] = l[p] * invS;
}

// ---------------- bicubic 2x upsample (Keys a=-0.5, half-pixel, jax boundary renorm) ----------------
__device__ __forceinline__ float keysw(float x) {
    x = fabsf(x);
    if (x <= 1.f)      return ((1.5f*x - 2.5f)*x)*x + 1.f;
    else if (x < 2.f)  return ((-0.5f*x + 2.5f)*x - 4.f)*x + 2.f;
    return 0.f;
}
__device__ __forceinline__ void cubw(int o, int n, int* base, float w[4]) {
    float cc = 0.5f * o - 0.25f;
    int bb = (int)floorf(cc);
    float t = cc - (float)bb;
    w[0] = keysw(1.f + t); w[1] = keysw(t); w[2] = keysw(1.f - t); w[3] = keysw(2.f - t);
    float s = 0.f;
    #pragma unroll
    for (int k = 0; k < 4; k++) {
        int ii = bb - 1 + k;
        if (ii < 0 || ii >= n) w[k] = 0.f;
        s += w[k];
    }
    float inv = 1.f / s;
    #pragma unroll
    for (int k = 0; k < 4; k++) w[k] *= inv;
    *base = bb - 1;
}
__global__ void bicubic2x_kernel(const float* __restrict__ src, float* __restrict__ dst,
                                 int H, int W) {
    int OH = 2*H, OW = 2*W;
    size_t idx = (size_t)blockIdx.x * blockDim.x + threadIdx.x;
    size_t total = (size_t)BATCH * CH * OH * OW;
    if (idx >= total) return;
    int ox = (int)(idx % OW); size_t t = idx / OW;
    int oy = (int)(t % OH);   size_t pl = t / OH;  // plane = b*CH + c
    int ix0; float wx[4]; cubw(ox, W, &ix0, wx);
    int iy0; float wy[4]; cubw(oy, H, &iy0, wy);
    const float* sp = src + pl * (size_t)(H*W);
    float acc = 0.f;
    #pragma unroll
    for (int ky = 0; ky < 4; ky++) {
        int iy = min(max(iy0 + ky, 0), H-1);
        float r = 0.f;
        #pragma unroll
        for (int kx = 0; kx < 4; kx++) {
            int ix = min(max(ix0 + kx, 0), W-1);
            r += wx[kx] * __ldg(&sp[(size_t)iy*W + ix]);
        }
        acc += wy[ky] * r;
    }
    dst[pl * (size_t)(OH*OW) + (size_t)oy*OW + ox] = acc;
}

// ---------------- adaptive 7x7 per-pixel conv over all channels ----------------
#define ATX 16
#define ATY 8
__global__ void __launch_bounds__(ATX*ATY) adapt_kernel(
        const float* __restrict__ hr, const float* __restrict__ comb,
        float* __restrict__ out, int GH, int GW) {
    __shared__ float sh[(ATY+6)*(ATX+6)];
    int tx = threadIdx.x % ATX, ty = threadIdx.x / ATX;
    int x0 = blockIdx.x * ATX, y0 = blockIdx.y * ATY;
    int b = blockIdx.z;
    int x = x0 + tx, y = y0 + ty;
    int plane = GH * GW;

    float w[NTAP];
    const float* wp = comb + ((size_t)b*plane + (size_t)y*GW + x) * NTAP;
    #pragma unroll
    for (int p = 0; p < NTAP; p++) w[p] = wp[p];

    const float* hp = hr + (size_t)b * CH * plane;
    float* op = out + (size_t)b * CH * plane;

    // precompute reflected halo coordinates once
    int gys[ATY+6], gxs[ATX+6];
    if (threadIdx.x < ATY+6) gys[0] = 0; // dummy to keep arrays in regs? compute per-load instead
    for (int c = 0; c < CH; c++) {
        const float* cp = hp + (size_t)c * plane;
        for (int i = threadIdx.x; i < (ATY+6)*(ATX+6); i += ATX*ATY) {
            int ly = i / (ATX+6), lx = i % (ATX+6);
            int gy = refl(y0 + ly - RAD, GH);
            int gx = refl(x0 + lx - RAD, GW);
            sh[i] = __ldg(&cp[(size_t)gy*GW + gx]);
        }
        __syncthreads();
        float acc = 0.f;
        #pragma unroll
        for (int i = 0; i < DIAM; i++)
            #pragma unroll
            for (int j = 0; j < DIAM; j++)
                acc += w[i*DIAM + j] * sh[(ty+i)*(ATX+6) + (tx+j)];
        op[(size_t)c*plane + (size_t)y*GW + x] = acc;
        __syncthreads();
    }
}

// ---------------- SGEMM: C[m][n] = sum_k A[m][k] B[k][n] + bias[m], per-batch ----------------
#define BM 128
#define BN 128
#define BK 8
#define TM 8
#define TN 8
__global__ void __launch_bounds__(256) gemm_kernel(
        const float* __restrict__ A, const float* __restrict__ Bmat,
        const float* __restrict__ bias, float* __restrict__ C,
        int M, int N, int K) {
    __shared__ float As[BK][BM];
    __shared__ float Bs[BK][BN];
    int bx = blockIdx.x * BN, by = blockIdx.y * BM;
    const float* Bb = Bmat + (size_t)blockIdx.z * K * N;
    float* Cb = C + (size_t)blockIdx.z * M * N;
    int tid = threadIdx.x;
    int tcol = (tid % 16) * TN;
    int trow = (tid / 16) * TM;
    float acc[TM][TN];
    #pragma unroll
    for (int m = 0; m < TM; m++)
        #pragma unroll
        for (int n = 0; n < TN; n++) acc[m][n] = 0.f;

    for (int k0 = 0; k0 < K; k0 += BK) {
        #pragma unroll
        for (int i = tid; i < BM*BK; i += 256) {
            int m = i / BK, k = i % BK;
            As[k][m] = A[(size_t)(by + m)*K + k0 + k];
        }
        #pragma unroll
        for (int i = tid; i < BK*BN; i += 256) {
            int k = i / BN, n = i % BN;
            Bs[k][n] = Bb[(size_t)(k0 + k)*N + bx + n];
        }
        __syncthreads();
        #pragma unroll
        for (int k = 0; k < BK; k++) {
            float4 a0 = *(const float4*)&As[k][trow];
            float4 a1 = *(const float4*)&As[k][trow+4];
            float4 b0 = *(const float4*)&Bs[k][tcol];
            float4 b1 = *(const float4*)&Bs[k][tcol+4];
            float av[TM] = {a0.x,a0.y,a0.z,a0.w,a1.x,a1.y,a1.z,a1.w};
            float bv[TN] = {b0.x,b0.y,b0.z,b0.w,b1.x,b1.y,b1.z,b1.w};
            #pragma unroll
            for (int m = 0; m < TM; m++)
                #pragma unroll
                for (int n = 0; n < TN; n++)
                    acc[m][n] += av[m] * bv[n];
        }
        __syncthreads();
    }
    #pragma unroll
    for (int m = 0; m < TM; m++) {
        float bi = bias[by + trow + m];
        float4 o0 = make_float4(acc[m][0]+bi, acc[m][1]+bi, acc[m][2]+bi, acc[m][3]+bi);
        float4 o1 = make_float4(acc[m][4]+bi, acc[m][5]+bi, acc[m][6]+bi, acc[m][7]+bi);
        float* dst = &Cb[(size_t)(by + trow + m)*N + bx + tcol];
        *(float4*)dst = o0;
        *(float4*)(dst + 4) = o1;
    }
}

// ---------------- host launch ----------------
extern "C" void kernel_launch(void* const* d_in, const int* in_sizes, int n_in,
                              void* d_out, int out_size) {
    const float* source   = (const float*)d_in[0];
    const float* guidance = (const float*)d_in[1];
    const float* u1w1 = (const float*)d_in[2];
    const float* u1b1 = (const float*)d_in[3];
    const float* u1w2 = (const float*)d_in[4];
    const float* u1b2 = (const float*)d_in[5];
    const float* u1rt = (const float*)d_in[6];
    const float* u1sg = (const float*)d_in[7];
    const float* u2w1 = (const float*)d_in[8];
    const float* u2b1 = (const float*)d_in[9];
    const float* u2w2 = (const float*)d_in[10];
    const float* u2b2 = (const float*)d_in[11];
    const float* u2rt = (const float*)d_in[12];
    const float* u2sg = (const float*)d_in[13];
    const float* fixw = (const float*)d_in[14];
    const float* fixb = (const float*)d_in[15];
    const float* prjw = (const float*)d_in[16];
    const float* prjb = (const float*)d_in[17];
    float* out = (float*)d_out;

    float *g1, *g2, *p1, *p2, *c1, *c2, *hr1, *s2, *hr2, *s4, *weff, *beff;
    cudaGetSymbolAddress((void**)&g1,  g_g1);
    cudaGetSymbolAddress((void**)&g2,  g_g2);
    cudaGetSymbolAddress((void**)&p1,  g_p1);
    cudaGetSymbolAddress((void**)&p2,  g_p2);
    cudaGetSymbolAddress((void**)&c1,  g_c1);
    cudaGetSymbolAddress((void**)&c2,  g_c2);
    cudaGetSymbolAddress((void**)&hr1, g_hr1);
    cudaGetSymbolAddress((void**)&s2,  g_s2);
    cudaGetSymbolAddress((void**)&hr2, g_hr2);
    cudaGetSymbolAddress((void**)&s4,  g_s4);
    cudaGetSymbolAddress((void**)&weff, g_weff);
    cudaGetSymbolAddress((void**)&beff, g_beff);

    // fused tail weights
    weff_kernel<<<(OUTC*CH + 255)/256, 256>>>(prjw, prjb, fixw, fixb, weff, beff);

    // pooled guidance
    pool_kernel<<<(BATCH*3*96*96   + 255)/256, 256>>>(guidance, g1, 96, 96, 8);
    pool_kernel<<<(BATCH*3*192*192 + 255)/256, 256>>>(guidance, g2, 192, 192, 4);

    // ---- stage 1: 48 -> 96 ----
    rproj_kernel<<<(BATCH*96*96 + 255)/256, 256>>>(g1, u1w1, u1b1, u1w2, u1b2, p1, 96, 96);
    comb_kernel <<<(BATCH*96*96 + 255)/256, 256>>>(p1, u1rt, u1sg, c1, 96, 96);
    {
        size_t tot = (size_t)BATCH*CH*96*96;
        bicubic2x_kernel<<<(unsigned)((tot + 255)/256), 256>>>(source, hr1, 48, 48);
    }
    adapt_kernel<<<dim3(96/ATX, 96/ATY, BATCH), ATX*ATY>>>(hr1, c1, s2, 96, 96);

    // ---- stage 2: 96 -> 192 ----
    rproj_kernel<<<(BATCH*192*192 + 255)/256, 256>>>(g2, u2w1, u2b1, u2w2, u2b2, p2, 192, 192);
    comb_kernel <<<(BATCH*192*192 + 255)/256, 256>>>(p2, u2rt, u2sg, c2, 192, 192);
    {
        size_t tot = (size_t)BATCH*CH*192*192;
        bicubic2x_kernel<<<(unsigned)((tot + 255)/256), 256>>>(s2, hr2, 96, 96);
    }
    adapt_kernel<<<dim3(192/ATX, 192/ATY, BATCH), ATX*ATY>>>(hr2, c2, s4, 192, 192);

    // ---- fused fixup+proj GEMM ----
    gemm_kernel<<<dim3(192*192/BN, OUTC/BM, BATCH), 256>>>(weff, s4, beff, out,
                                                           OUTC, 192*192, CH);
}

// round 2
// speedup vs baseline: 1.5119x; 1.5119x over previous
#include <cuda_runtime.h>
#include <math.h>
#include <stdint.h>

#define BATCH 8
#define CH    384
#define OUTC  256
#define KD    32
#define RAD   3
#define DIAM  7
#define NTAP  49

// ---------------- scratch (static device globals; no allocation) ----------------
__device__ float g_g1  [BATCH*3*96*96];
__device__ float g_g2  [BATCH*3*192*192];
__device__ float g_p1  [BATCH*96*96*KD];
__device__ float g_p2  [BATCH*192*192*KD];
__device__ float g_c1  [BATCH*96*96*NTAP];
__device__ float g_c2  [BATCH*192*192*NTAP];
__device__ float g_hr1 [(size_t)BATCH*CH*96*96];
__device__ float g_s2  [(size_t)BATCH*CH*96*96];
__device__ float g_hr2 [(size_t)BATCH*CH*192*192];
__device__ float g_s4  [(size_t)BATCH*CH*192*192];
__device__ float g_weff[OUTC*CH];
__device__ float g_beff[OUTC];

__device__ __forceinline__ int refl(int i, int n) {
    if (i < 0) i = -i;
    if (i >= n) i = 2*n - 2 - i;
    return i;
}

// ---------------- W_eff = P + 0.1 P F ; b_eff = pb + 0.1 P fb ----------------
__global__ void weff_kernel(const float* __restrict__ Pw, const float* __restrict__ pb,
                            const float* __restrict__ Fw, const float* __restrict__ fb,
                            float* __restrict__ Weff, float* __restrict__ beff) {
    int idx = blockIdx.x * blockDim.x + threadIdx.x;
    if (idx < OUTC*CH) {
        int o = idx / CH, c = idx % CH;
        float acc = 0.f;
        #pragma unroll 4
        for (int k = 0; k < CH; k++) acc += Pw[o*CH + k] * Fw[k*CH + c];
        Weff[idx] = Pw[o*CH + c] + 0.1f * acc;
    }
    if (idx < OUTC) {
        float a = 0.f;
        for (int k = 0; k < CH; k++) a += Pw[idx*CH + k] * fb[k];
        beff[idx] = pb[idx] + 0.1f * a;
    }
}

// ---------------- adaptive avg pool (exact integer factor) ----------------
__global__ void pool_kernel(const float* __restrict__ g, float* __restrict__ out,
                            int OH, int OW, int F) {
    int idx = blockIdx.x * blockDim.x + threadIdx.x;
    int total = BATCH * 3 * OH * OW;
    if (idx >= total) return;
    int ox = idx % OW; int t = idx / OW;
    int oy = t % OH;   t /= OH;
    int c  = t % 3;    int b = t / 3;
    const float* p = g + (((size_t)(b*3 + c)*768) + (size_t)oy*F)*768 + (size_t)ox*F;
    float s = 0.f;
    for (int i = 0; i < F; i++)
        for (int j = 0; j < F; j++)
            s += p[i*768 + j];
    out[idx] = s / (float)(F*F);
}

// ---------------- range projection MLP: 3 -> 32 (gelu) -> 32, pixel-major out ----------------
__global__ void rproj_kernel(const float* __restrict__ g,
                             const float* __restrict__ w1, const float* __restrict__ b1,
                             const float* __restrict__ w2, const float* __restrict__ b2,
                             float* __restrict__ proj, int GH, int GW) {
    __shared__ float sw1[KD*3], sb1[KD], sw2[KD*KD], sb2[KD];
    int tid = threadIdx.x;
    for (int i = tid; i < KD*3;  i += blockDim.x) sw1[i] = w1[i];
    for (int i = tid; i < KD;    i += blockDim.x) { sb1[i] = b1[i]; sb2[i] = b2[i]; }
    for (int i = tid; i < KD*KD; i += blockDim.x) sw2[i] = w2[i];
    __syncthreads();
    int idx = blockIdx.x * blockDim.x + tid;
    int plane = GH * GW;
    if (idx >= BATCH * plane) return;
    int b = idx / plane, pix = idx % plane;
    float g0 = g[(size_t)(b*3 + 0)*plane + pix];
    float g1v = g[(size_t)(b*3 + 1)*plane + pix];
    float g2v = g[(size_t)(b*3 + 2)*plane + pix];
    float h[KD];
    #pragma unroll
    for (int o = 0; o < KD; o++) {
        float x = sw1[o*3]*g0 + sw1[o*3+1]*g1v + sw1[o*3+2]*g2v + sb1[o];
        float u = 0.7978845608028654f * (x + 0.044715f * x*x*x);
        h[o] = 0.5f * x * (1.f + tanhf(u));
    }
    float* op = proj + (size_t)idx * KD;
    #pragma unroll
    for (int o = 0; o < KD; o++) {
        float s = sb2[o];
        #pragma unroll
        for (int k = 0; k < KD; k++) s += sw2[o*KD + k] * h[k];
        op[o] = s;
    }
}

// ---------------- combined 49-tap kernel: softmax(range) * spatial, normalized ----------------
__global__ void comb_kernel(const float* __restrict__ proj,
                            const float* __restrict__ rt_p, const float* __restrict__ sig_p,
                            float* __restrict__ comb, int GH, int GW) {
    int idx = blockIdx.x * blockDim.x + threadIdx.x;
    int plane = GH * GW;
    if (idx >= BATCH * plane) return;
    int b = idx / plane, pix = idx % plane;
    int y = pix / GW, x = pix % GW;
    const float4* base4 = (const float4*)(proj + (size_t)b*plane*KD);

    float4 cv[KD/4];
    const float4* cp = base4 + (size_t)pix * (KD/4);
    #pragma unroll
    for (int q = 0; q < KD/4; q++) cv[q] = cp[q];

    float temp = expf(rt_p[0]);
    temp = fminf(fmaxf(temp, 1e-4f), 1e4f);
    float sig = sig_p[0];
    float inv2s2 = 1.f / (2.f * sig * sig);

    int ys[DIAM], xs[DIAM];
    #pragma unroll
    for (int i = 0; i < DIAM; i++) { ys[i] = refl(y + i - RAD, GH); xs[i] = refl(x + i - RAD, GW); }

    float l[NTAP];
    float m = -1e30f;
    #pragma unroll
    for (int i = 0; i < DIAM; i++) {
        #pragma unroll
        for (int j = 0; j < DIAM; j++) {
            const float4* np = base4 + (size_t)(ys[i]*GW + xs[j]) * (KD/4);
            float d = 0.f;
            #pragma unroll
            for (int q = 0; q < KD/4; q++) {
                float4 nv = __ldg(&np[q]);
                d += cv[q].x*nv.x + cv[q].y*nv.y + cv[q].z*nv.z + cv[q].w*nv.w;
            }
            d *= temp;
            l[i*DIAM + j] = d;
            m = fmaxf(m, d);
        }
    }
    float Z = 0.f;
    #pragma unroll
    for (int p = 0; p < NTAP; p++) { l[p] = expf(l[p] - m); Z += l[p]; }
    float invZ = 1.f / Z;
    float S = 0.f;
    #pragma unroll
    for (int p = 0; p < NTAP; p++) {
        int i = p / DIAM, j = p % DIAM;
        float dy = (i - 3) * (1.f/3.f), dx = (j - 3) * (1.f/3.f);
        float sp = expf(-(dx*dx + dy*dy) * inv2s2);
        l[p] = (l[p] * invZ) * sp;
        S += l[p];
    }
    S = fmaxf(S, 1e-7f);
    float invS = 1.f / S;
    float* op = comb + (size_t)idx * NTAP;
    #pragma unroll
    for (int p = 0; p < NTAP; p++) op[p] = l[p] * invS;
}

// ---------------- bicubic 2x upsample, 2x2 outputs per thread ----------------
__device__ __forceinline__ float keysw(float x) {
    x = fabsf(x);
    if (x <= 1.f)      return ((1.5f*x - 2.5f)*x)*x + 1.f;
    else if (x < 2.f)  return ((-0.5f*x + 2.5f)*x - 4.f)*x + 2.f;
    return 0.f;
}
// weights for output coord o (taps at indices floor(0.5o-0.25)-1 + k)
__device__ __forceinline__ void cubw(int o, int n, int* base, float w[4]) {
    float cc = 0.5f * o - 0.25f;
    int bb = (int)floorf(cc);
    float t = cc - (float)bb;
    w[0] = keysw(1.f + t); w[1] = keysw(t); w[2] = keysw(1.f - t); w[3] = keysw(2.f - t);
    float s = 0.f;
    #pragma unroll
    for (int k = 0; k < 4; k++) {
        int ii = bb - 1 + k;
        if (ii < 0 || ii >= n) w[k] = 0.f;
        s += w[k];
    }
    float inv = 1.f / s;
    #pragma unroll
    for (int k = 0; k < 4; k++) w[k] *= inv;
    *base = bb - 1;
}
__global__ void bicubic2x2_kernel(const float* __restrict__ src, float* __restrict__ dst,
                                  int H, int W) {
    int OW = 2*W, OH = 2*H;
    size_t idx = (size_t)blockIdx.x * blockDim.x + threadIdx.x;
    size_t total = (size_t)BATCH * CH * H * W;
    if (idx >= total) return;
    int ix = (int)(idx % W); size_t t = idx / W;
    int iy = (int)(t % H);   size_t pl = t / H;

    int dum;
    float wx0[4], wx1[4], wy0[4], wy1[4];
    cubw(2*ix,   W, &dum, wx0);   // taps ix-2..ix+1 -> window cols 0..3
    cubw(2*ix+1, W, &dum, wx1);   // taps ix-1..ix+2 -> window cols 1..4
    cubw(2*iy,   H, &dum, wy0);
    cubw(2*iy+1, H, &dum, wy1);

    const float* sp = src + pl * (size_t)(H*W);
    float v[5][5];
    #pragma unroll
    for (int r = 0; r < 5; r++) {
        int ry = min(max(iy - 2 + r, 0), H-1);
        const float* rp = sp + (size_t)ry * W;
        #pragma unroll
        for (int c = 0; c < 5; c++) {
            int rx = min(max(ix - 2 + c, 0), W-1);
            v[r][c] = __ldg(&rp[rx]);
        }
    }
    float h0[5], h1[5];
    #pragma unroll
    for (int r = 0; r < 5; r++) {
        h0[r] = wx0[0]*v[r][0] + wx0[1]*v[r][1] + wx0[2]*v[r][2] + wx0[3]*v[r][3];
        h1[r] = wx1[0]*v[r][1] + wx1[1]*v[r][2] + wx1[2]*v[r][3] + wx1[3]*v[r][4];
    }
    float o00 = wy0[0]*h0[0] + wy0[1]*h0[1] + wy0[2]*h0[2] + wy0[3]*h0[3];
    float o01 = wy0[0]*h1[0] + wy0[1]*h1[1] + wy0[2]*h1[2] + wy0[3]*h1[3];
    float o10 = wy1[0]*h0[1] + wy1[1]*h0[2] + wy1[2]*h0[3] + wy1[3]*h0[4];
    float o11 = wy1[0]*h1[1] + wy1[1]*h1[2] + wy1[2]*h1[3] + wy1[3]*h1[4];

    float* dp = dst + pl * (size_t)(OH*OW);
    *(float2*)&dp[(size_t)(2*iy)  *OW + 2*ix] = make_float2(o00, o01);
    *(float2*)&dp[(size_t)(2*iy+1)*OW + 2*ix] = make_float2(o10, o11);
}

// ---------------- adaptive 7x7 per-pixel conv, double-buffered channel halo ----------------
#define ATX 16
#define ATY 16
#define HALO ((ATY+6)*(ATX+6))   // 484
__global__ void __launch_bounds__(256) adapt_kernel(
        const float* __restrict__ hr, const float* __restrict__ comb,
        float* __restrict__ out, int GH, int GW) {
    __shared__ float sh[2][HALO];
    __shared__ int soff[HALO];
    int tid = threadIdx.x;
    int tx = tid % ATX, ty = tid / ATX;
    int x0 = blockIdx.x * ATX, y0 = blockIdx.y * ATY;
    int b = blockIdx.z;
    int x = x0 + tx, y = y0 + ty;
    int plane = GH * GW;

    for (int i = tid; i < HALO; i += 256) {
        int ly = i / (ATX+6), lx = i % (ATX+6);
        soff[i] = refl(y0 + ly - RAD, GH)*GW + refl(x0 + lx - RAD, GW);
    }

    float w[NTAP];
    const float* wp = comb + ((size_t)b*plane + (size_t)y*GW + x) * NTAP;
    #pragma unroll
    for (int p = 0; p < NTAP; p++) w[p] = wp[p];

    const float* hp = hr + (size_t)b * CH * plane;
    float* op = out + (size_t)b * CH * plane + (size_t)y*GW + x;

    __syncthreads();
    int h0 = tid, h1 = tid + 256;
    int off0 = soff[h0];
    int off1 = (h1 < HALO) ? soff[h1] : 0;

    // prologue: channel 0
    sh[0][h0] = hp[off0];
    if (h1 < HALO) sh[0][h1] = hp[off1];
    __syncthreads();

    for (int c = 0; c < CH; c++) {
        int cur = c & 1;
        float n0 = 0.f, n1 = 0.f;
        if (c + 1 < CH) {
            const float* cpn = hp + (size_t)(c+1) * plane;
            n0 = cpn[off0];
            if (h1 < HALO) n1 = cpn[off1];
        }
        float acc = 0.f;
        #pragma unroll
        for (int i = 0; i < DIAM; i++)
            #pragma unroll
            for (int j = 0; j < DIAM; j++)
                acc += w[i*DIAM + j] * sh[cur][(ty+i)*(ATX+6) + (tx+j)];
        op[(size_t)c * plane] = acc;
        if (c + 1 < CH) {
            sh[cur^1][h0] = n0;
            if (h1 < HALO) sh[cur^1][h1] = n1;
        }
        __syncthreads();
    }
}

// ---------------- tf32 tensor-core GEMM: C[o][n] = sum_k W[o][k] B[k][n] + bias[o] ----------------
#define GBM 128
#define GBN 128
#define GBK 16
#define GNK (CH/GBK)   // 24

__device__ __forceinline__ uint32_t f2tf32(float x) {
    uint32_t u;
    asm("cvt.rna.tf32.f32 %0, %1;" : "=r"(u) : "f"(x));
    return u;
}
__device__ __forceinline__ void mma_tf32(float c[4],
        uint32_t a0, uint32_t a1, uint32_t a2, uint32_t a3,
        uint32_t b0, uint32_t b1) {
    asm volatile(
        "mma.sync.aligned.m16n8k8.row.col.f32.tf32.tf32.f32 "
        "{%0,%1,%2,%3},{%4,%5,%6,%7},{%8,%9},{%0,%1,%2,%3};\n"
        : "+f"(c[0]), "+f"(c[1]), "+f"(c[2]), "+f"(c[3])
        : "r"(a0), "r"(a1), "r"(a2), "r"(a3), "r"(b0), "r"(b1));
}

__global__ void __launch_bounds__(256) gemm_tf32_kernel(
        const float* __restrict__ A, const float* __restrict__ Bmat,
        const float* __restrict__ bias, float* __restrict__ C, int N) {
    __shared__ uint32_t As[2][GBM][20];    // [m][k] padded: stride 20 (conflict-free frags)
    __shared__ uint32_t Bs[2][GBK][136];   // [k][n] padded: stride 136

    int tid = threadIdx.x;
    int warp = tid / 32, lane = tid % 32;
    int wm = warp / 4, wn = warp % 4;      // warp tile: 64(M) x 32(N)
    int g = lane / 4, tig = lane % 4;
    int bx = blockIdx.x * GBN, by = blockIdx.y * GBM;
    const float* Bb = Bmat + (size_t)blockIdx.z * CH * N;
    float* Cb = C + (size_t)blockIdx.z * OUTC * N;

    float acc[4][4][4];
    #pragma unroll
    for (int mi = 0; mi < 4; mi++)
        #pragma unroll
        for (int ni = 0; ni < 4; ni++)
            #pragma unroll
            for (int q = 0; q < 4; q++) acc[mi][ni][q] = 0.f;

    int aid0 = tid, aid1 = tid + 256;            // 512 float4 of A tile
    int ar0 = aid0 >> 2, ac0 = (aid0 & 3) << 2;
    int ar1 = aid1 >> 2, ac1 = (aid1 & 3) << 2;
    int br0 = aid0 >> 5, bc0 = (aid0 & 31) << 2; // 512 float4 of B tile
    int br1 = aid1 >> 5, bc1 = (aid1 & 31) << 2;

    // prologue: tile 0
    float4 ra0 = *(const float4*)&A[(size_t)(by + ar0)*CH + ac0];
    float4 ra1 = *(const float4*)&A[(size_t)(by + ar1)*CH + ac1];
    float4 rb0 = *(const float4*)&Bb[(size_t)br0*N + bx + bc0];
    float4 rb1 = *(const float4*)&Bb[(size_t)br1*N + bx + bc1];
    {
        As[0][ar0][ac0+0]=f2tf32(ra0.x); As[0][ar0][ac0+1]=f2tf32(ra0.y);
        As[0][ar0][ac0+2]=f2tf32(ra0.z); As[0][ar0][ac0+3]=f2tf32(ra0.w);
        As[0][ar1][ac1+0]=f2tf32(ra1.x); As[0][ar1][ac1+1]=f2tf32(ra1.y);
        As[0][ar1][ac1+2]=f2tf32(ra1.z); As[0][ar1][ac1+3]=f2tf32(ra1.w);
        uint4 u0 = make_uint4(f2tf32(rb0.x), f2tf32(rb0.y), f2tf32(rb0.z), f2tf32(rb0.w));
        uint4 u1 = make_uint4(f2tf32(rb1.x), f2tf32(rb1.y), f2tf32(rb1.z), f2tf32(rb1.w));
        *(uint4*)&Bs[0][br0][bc0] = u0;
        *(uint4*)&Bs[0][br1][bc1] = u1;
    }
    __syncthreads();

    for (int kt = 0; kt < GNK; kt++) {
        int cur = kt & 1;
        if (kt + 1 < GNK) {
            int k0 = (kt + 1) * GBK;
            ra0 = *(const float4*)&A[(size_t)(by + ar0)*CH + k0 + ac0];
            ra1 = *(const float4*)&A[(size_t)(by + ar1)*CH + k0 + ac1];
            rb0 = *(const float4*)&Bb[(size_t)(k0 + br0)*N + bx + bc0];
            rb1 = *(const float4*)&Bb[(size_t)(k0 + br1)*N + bx + bc1];
        }
        #pragma unroll
        for (int ksub = 0; ksub < 2; ksub++) {
            int kb = ksub * 8;
            uint32_t af[4][4], bf[4][2];
            #pragma unroll
            for (int mi = 0; mi < 4; mi++) {
                int row = wm*64 + mi*16 + g;
                af[mi][0] = As[cur][row  ][kb + tig];
                af[mi][1] = As[cur][row+8][kb + tig];
                af[mi][2] = As[cur][row  ][kb + tig + 4];
                af[mi][3] = As[cur][row+8][kb + tig + 4];
            }
            #pragma unroll
            for (int ni = 0; ni < 4; ni++) {
                int col = wn*32 + ni*8 + g;
                bf[ni][0] = Bs[cur][kb + tig    ][col];
                bf[ni][1] = Bs[cur][kb + tig + 4][col];
            }
            #pragma unroll
            for (int mi = 0; mi < 4; mi++)
                #pragma unroll
                for (int ni = 0; ni < 4; ni++)
                    mma_tf32(acc[mi][ni], af[mi][0], af[mi][1], af[mi][2], af[mi][3],
                             bf[ni][0], bf[ni][1]);
        }
        if (kt + 1 < GNK) {
            int nxt = cur ^ 1;
            As[nxt][ar0][ac0+0]=f2tf32(ra0.x); As[nxt][ar0][ac0+1]=f2tf32(ra0.y);
            As[nxt][ar0][ac0+2]=f2tf32(ra0.z); As[nxt][ar0][ac0+3]=f2tf32(ra0.w);
            As[nxt][ar1][ac1+0]=f2tf32(ra1.x); As[nxt][ar1][ac1+1]=f2tf32(ra1.y);
            As[nxt][ar1][ac1+2]=f2tf32(ra1.z); As[nxt][ar1][ac1+3]=f2tf32(ra1.w);
            uint4 u0 = make_uint4(f2tf32(rb0.x), f2tf32(rb0.y), f2tf32(rb0.z), f2tf32(rb0.w));
            uint4 u1 = make_uint4(f2tf32(rb1.x), f2tf32(rb1.y), f2tf32(rb1.z), f2tf32(rb1.w));
            *(uint4*)&Bs[nxt][br0][bc0] = u0;
            *(uint4*)&Bs[nxt][br1][bc1] = u1;
        }
        __syncthreads();
    }

    #pragma unroll
    for (int mi = 0; mi < 4; mi++) {
        int r0 = by + wm*64 + mi*16 + g;
        float bi0 = bias[r0], bi1 = bias[r0 + 8];
        #pragma unroll
        for (int ni = 0; ni < 4; ni++) {
            int cc = bx + wn*32 + ni*8 + tig*2;
            *(float2*)&Cb[(size_t)r0*N + cc]     = make_float2(acc[mi][ni][0]+bi0, acc[mi][ni][1]+bi0);
            *(float2*)&Cb[(size_t)(r0+8)*N + cc] = make_float2(acc[mi][ni][2]+bi1, acc[mi][ni][3]+bi1);
        }
    }
}

// ---------------- host launch ----------------
extern "C" void kernel_launch(void* const* d_in, const int* in_sizes, int n_in,
                              void* d_out, int out_size) {
    const float* source   = (const float*)d_in[0];
    const float* guidance = (const float*)d_in[1];
    const float* u1w1 = (const float*)d_in[2];
    const float* u1b1 = (const float*)d_in[3];
    const float* u1w2 = (const float*)d_in[4];
    const float* u1b2 = (const float*)d_in[5];
    const float* u1rt = (const float*)d_in[6];
    const float* u1sg = (const float*)d_in[7];
    const float* u2w1 = (const float*)d_in[8];
    const float* u2b1 = (const float*)d_in[9];
    const float* u2w2 = (const float*)d_in[10];
    const float* u2b2 = (const float*)d_in[11];
    const float* u2rt = (const float*)d_in[12];
    const float* u2sg = (const float*)d_in[13];
    const float* fixw = (const float*)d_in[14];
    const float* fixb = (const float*)d_in[15];
    const float* prjw = (const float*)d_in[16];
    const float* prjb = (const float*)d_in[17];
    float* out = (float*)d_out;

    float *g1, *g2, *p1, *p2, *c1, *c2, *hr1, *s2, *hr2, *s4, *weff, *beff;
    cudaGetSymbolAddress((void**)&g1,  g_g1);
    cudaGetSymbolAddress((void**)&g2,  g_g2);
    cudaGetSymbolAddress((void**)&p1,  g_p1);
    cudaGetSymbolAddress((void**)&p2,  g_p2);
    cudaGetSymbolAddress((void**)&c1,  g_c1);
    cudaGetSymbolAddress((void**)&c2,  g_c2);
    cudaGetSymbolAddress((void**)&hr1, g_hr1);
    cudaGetSymbolAddress((void**)&s2,  g_s2);
    cudaGetSymbolAddress((void**)&hr2, g_hr2);
    cudaGetSymbolAddress((void**)&s4,  g_s4);
    cudaGetSymbolAddress((void**)&weff, g_weff);
    cudaGetSymbolAddress((void**)&beff, g_beff);

    weff_kernel<<<(OUTC*CH + 255)/256, 256>>>(prjw, prjb, fixw, fixb, weff, beff);

    pool_kernel<<<(BATCH*3*96*96   + 255)/256, 256>>>(guidance, g1, 96, 96, 8);
    pool_kernel<<<(BATCH*3*192*192 + 255)/256, 256>>>(guidance, g2, 192, 192, 4);

    // ---- stage 1: 48 -> 96 ----
    rproj_kernel<<<(BATCH*96*96 + 255)/256, 256>>>(g1, u1w1, u1b1, u1w2, u1b2, p1, 96, 96);
    comb_kernel <<<(BATCH*96*96 + 255)/256, 256>>>(p1, u1rt, u1sg, c1, 96, 96);
    {
        size_t tot = (size_t)BATCH*CH*48*48;
        bicubic2x2_kernel<<<(unsigned)((tot + 255)/256), 256>>>(source, hr1, 48, 48);
    }
    adapt_kernel<<<dim3(96/ATX, 96/ATY, BATCH), 256>>>(hr1, c1, s2, 96, 96);

    // ---- stage 2: 96 -> 192 ----
    rproj_kernel<<<(BATCH*192*192 + 255)/256, 256>>>(g2, u2w1, u2b1, u2w2, u2b2, p2, 192, 192);
    comb_kernel <<<(BATCH*192*192 + 255)/256, 256>>>(p2, u2rt, u2sg, c2, 192, 192);
    {
        size_t tot = (size_t)BATCH*CH*96*96;
        bicubic2x2_kernel<<<(unsigned)((tot + 255)/256), 256>>>(s2, hr2, 96, 96);
    }
    adapt_kernel<<<dim3(192/ATX, 192/ATY, BATCH), 256>>>(hr2, c2, s4, 192, 192);

    // ---- fused fixup+proj GEMM (tf32 tensor cores) ----
    gemm_tf32_kernel<<<dim3(192*192/GBN, OUTC/GBM, BATCH), 256>>>(weff, s4, beff, out, 192*192);
}

// round 3
// speedup vs baseline: 1.5995x; 1.0579x over previous
#include <cuda_runtime.h>
#include <math.h>
#include <stdint.h>

#define BATCH 8
#define CH    384
#define OUTC  256
#define KD    32
#define RAD   3
#define DIAM  7
#define NTAP  49

// ---------------- scratch (static device globals; no allocation) ----------------
__device__ float g_g1  [BATCH*3*96*96];
__device__ float g_g2  [BATCH*3*192*192];
__device__ float g_p1  [BATCH*96*96*KD];
__device__ float g_p2  [BATCH*192*192*KD];
__device__ float g_c1  [BATCH*96*96*NTAP];
__device__ float g_c2  [BATCH*192*192*NTAP];
__device__ float g_s2  [(size_t)BATCH*CH*96*96];
__device__ float g_s4  [(size_t)BATCH*CH*192*192];
__device__ float g_weff[OUTC*CH];
__device__ float g_beff[OUTC];

__device__ __forceinline__ int refl(int i, int n) {
    if (i < 0) i = -i;
    if (i >= n) i = 2*n - 2 - i;
    return i;
}

__device__ __forceinline__ uint32_t f2tf32(float x) {
    uint32_t u;
    asm("cvt.rna.tf32.f32 %0, %1;" : "=r"(u) : "f"(x));
    return u;
}

// ---------------- W_eff = P + 0.1 P F ; b_eff = pb + 0.1 P fb (tf32-rounded W) ----------------
__global__ void weff_kernel(const float* __restrict__ Pw, const float* __restrict__ pb,
                            const float* __restrict__ Fw, const float* __restrict__ fb,
                            float* __restrict__ Weff, float* __restrict__ beff) {
    int idx = blockIdx.x * blockDim.x + threadIdx.x;
    if (idx < OUTC*CH) {
        int o = idx / CH, c = idx % CH;
        float acc = 0.f;
        #pragma unroll 4
        for (int k = 0; k < CH; k++) acc += Pw[o*CH + k] * Fw[k*CH + c];
        Weff[idx] = __uint_as_float(f2tf32(Pw[o*CH + c] + 0.1f * acc));
    }
    if (idx < OUTC) {
        float a = 0.f;
        for (int k = 0; k < CH; k++) a += Pw[idx*CH + k] * fb[k];
        beff[idx] = pb[idx] + 0.1f * a;
    }
}

// ---------------- adaptive avg pool (exact integer factor) ----------------
__global__ void pool_kernel(const float* __restrict__ g, float* __restrict__ out,
                            int OH, int OW, int F) {
    int idx = blockIdx.x * blockDim.x + threadIdx.x;
    int total = BATCH * 3 * OH * OW;
    if (idx >= total) return;
    int ox = idx % OW; int t = idx / OW;
    int oy = t % OH;   t /= OH;
    int c  = t % 3;    int b = t / 3;
    const float* p = g + (((size_t)(b*3 + c)*768) + (size_t)oy*F)*768 + (size_t)ox*F;
    float s = 0.f;
    for (int i = 0; i < F; i++)
        for (int j = 0; j < F; j++)
            s += p[i*768 + j];
    out[idx] = s / (float)(F*F);
}

// ---------------- range projection MLP: 3 -> 32 (gelu) -> 32, pixel-major out ----------------
__global__ void rproj_kernel(const float* __restrict__ g,
                             const float* __restrict__ w1, const float* __restrict__ b1,
                             const float* __restrict__ w2, const float* __restrict__ b2,
                             float* __restrict__ proj, int GH, int GW) {
    __shared__ float sw1[KD*3], sb1[KD], sw2[KD*KD], sb2[KD];
    int tid = threadIdx.x;
    for (int i = tid; i < KD*3;  i += blockDim.x) sw1[i] = w1[i];
    for (int i = tid; i < KD;    i += blockDim.x) { sb1[i] = b1[i]; sb2[i] = b2[i]; }
    for (int i = tid; i < KD*KD; i += blockDim.x) sw2[i] = w2[i];
    __syncthreads();
    int idx = blockIdx.x * blockDim.x + tid;
    int plane = GH * GW;
    if (idx >= BATCH * plane) return;
    int b = idx / plane, pix = idx % plane;
    float g0 = g[(size_t)(b*3 + 0)*plane + pix];
    float g1v = g[(size_t)(b*3 + 1)*plane + pix];
    float g2v = g[(size_t)(b*3 + 2)*plane + pix];
    float h[KD];
    #pragma unroll
    for (int o = 0; o < KD; o++) {
        float x = sw1[o*3]*g0 + sw1[o*3+1]*g1v + sw1[o*3+2]*g2v + sb1[o];
        float u = 0.7978845608028654f * (x + 0.044715f * x*x*x);
        h[o] = 0.5f * x * (1.f + tanhf(u));
    }
    float* op = proj + (size_t)idx * KD;
    #pragma unroll
    for (int o = 0; o < KD; o++) {
        float s = sb2[o];
        #pragma unroll
        for (int k = 0; k < KD; k++) s += sw2[o*KD + k] * h[k];
        op[o] = s;
    }
}

// ---------------- combined 49-tap kernel: softmax(range) * spatial, normalized ----------------
__global__ void comb_kernel(const float* __restrict__ proj,
                            const float* __restrict__ rt_p, const float* __restrict__ sig_p,
                            float* __restrict__ comb, int GH, int GW) {
    int idx = blockIdx.x * blockDim.x + threadIdx.x;
    int plane = GH * GW;
    if (idx >= BATCH * plane) return;
    int b = idx / plane, pix = idx % plane;
    int y = pix / GW, x = pix % GW;
    const float4* base4 = (const float4*)(proj + (size_t)b*plane*KD);

    float4 cv[KD/4];
    const float4* cp = base4 + (size_t)pix * (KD/4);
    #pragma unroll
    for (int q = 0; q < KD/4; q++) cv[q] = cp[q];

    float temp = expf(rt_p[0]);
    temp = fminf(fmaxf(temp, 1e-4f), 1e4f);
    float sig = sig_p[0];
    float inv2s2 = 1.f / (2.f * sig * sig);

    int ys[DIAM], xs[DIAM];
    #pragma unroll
    for (int i = 0; i < DIAM; i++) { ys[i] = refl(y + i - RAD, GH); xs[i] = refl(x + i - RAD, GW); }

    float l[NTAP];
    float m = -1e30f;
    #pragma unroll
    for (int i = 0; i < DIAM; i++) {
        #pragma unroll
        for (int j = 0; j < DIAM; j++) {
            const float4* np = base4 + (size_t)(ys[i]*GW + xs[j]) * (KD/4);
            float d = 0.f;
            #pragma unroll
            for (int q = 0; q < KD/4; q++) {
                float4 nv = __ldg(&np[q]);
                d += cv[q].x*nv.x + cv[q].y*nv.y + cv[q].z*nv.z + cv[q].w*nv.w;
            }
            d *= temp;
            l[i*DIAM + j] = d;
            m = fmaxf(m, d);
        }
    }
    float Z = 0.f;
    #pragma unroll
    for (int p = 0; p < NTAP; p++) { l[p] = expf(l[p] - m); Z += l[p]; }
    float invZ = 1.f / Z;
    float S = 0.f;
    #pragma unroll
    for (int p = 0; p < NTAP; p++) {
        int i = p / DIAM, j = p % DIAM;
        float dy = (i - 3) * (1.f/3.f), dx = (j - 3) * (1.f/3.f);
        float sp = expf(-(dx*dx + dy*dy) * inv2s2);
        l[p] = (l[p] * invZ) * sp;
        S += l[p];
    }
    S = fmaxf(S, 1e-7f);
    float invS = 1.f / S;
    float* op = comb + (size_t)idx * NTAP;
    #pragma unroll
    for (int p = 0; p < NTAP; p++) op[p] = l[p] * invS;
}

// ---------------- bicubic weight helper (Keys a=-0.5, half-pixel, jax boundary renorm) ----------------
__device__ __forceinline__ float keysw(float x) {
    x = fabsf(x);
    if (x <= 1.f)      return ((1.5f*x - 2.5f)*x)*x + 1.f;
    else if (x < 2.f)  return ((-0.5f*x + 2.5f)*x - 4.f)*x + 2.f;
    return 0.f;
}
__device__ __forceinline__ void cubw(int o, int n, int* base, float w[4]) {
    float cc = 0.5f * o - 0.25f;
    int bb = (int)floorf(cc);
    float t = cc - (float)bb;
    w[0] = keysw(1.f + t); w[1] = keysw(t); w[2] = keysw(1.f - t); w[3] = keysw(2.f - t);
    float s = 0.f;
    #pragma unroll
    for (int k = 0; k < 4; k++) {
        int ii = bb - 1 + k;
        if (ii < 0 || ii >= n) w[k] = 0.f;
        s += w[k];
    }
    float inv = 1.f / s;
    #pragma unroll
    for (int k = 0; k < 4; k++) w[k] *= inv;
    *base = bb - 1;
}

// ---------------- FUSED bicubic 2x + adaptive 7x7 conv ----------------
// Input src [B,CH,H,W] -> output out [B,CH,2H,2W], per-pixel 7x7 weights from comb.
#define ATX 16
#define ATY 16
#define SRCT 16              // staged source tile 16x16
#define HLY (ATY+6)          // 22
#define HLX (ATX+6)          // 22
__global__ void __launch_bounds__(256) jbu_fused_kernel(
        const float* __restrict__ src, const float* __restrict__ comb,
        float* __restrict__ out, int H, int W, int do_round) {
    int GH = 2*H, GW = 2*W;
    __shared__ float s2t[SRCT][SRCT+1];
    __shared__ float tmpH[SRCT][HLX+2];
    __shared__ float hrt[HLY][HLX+2];
    __shared__ float wxs[HLX][4]; __shared__ int cxs[HLX][4];
    __shared__ float wys[HLY][4]; __shared__ int rys[HLY][4];

    int tid = threadIdx.x;
    int tx = tid % ATX, ty = tid / ATX;
    int x0 = blockIdx.x * ATX, y0 = blockIdx.y * ATY;
    int b = blockIdx.z;
    int x = x0 + tx, y = y0 + ty;
    int plane = GH * GW;
    int sx0 = x0/2 - 4, sy0 = y0/2 - 4;

    // per-block bicubic weight/index tables (reflect on hr grid, clamp on src grid)
    if (tid < HLX + HLY) {
        if (tid < HLX) {
            int l = tid;
            int gx = refl(x0 - RAD + l, GW);
            int base; float w[4]; cubw(gx, W, &base, w);
            #pragma unroll
            for (int k = 0; k < 4; k++) {
                cxs[l][k] = min(max(base + k, 0), W-1) - sx0;
                wxs[l][k] = w[k];
            }
        } else {
            int l = tid - HLX;
            int gy = refl(y0 - RAD + l, GH);
            int base; float w[4]; cubw(gy, H, &base, w);
            #pragma unroll
            for (int k = 0; k < 4; k++) {
                rys[l][k] = min(max(base + k, 0), H-1) - sy0;
                wys[l][k] = w[k];
            }
        }
    }

    // per-pixel conv weights
    float w[NTAP];
    const float* wp = comb + ((size_t)b*plane + (size_t)y*GW + x) * NTAP;
    #pragma unroll
    for (int p = 0; p < NTAP; p++) w[p] = wp[p];

    // staged src load coords (clamped)
    int lr = tid >> 4, lc = tid & 15;
    int gr = min(max(sy0 + lr, 0), H-1);
    int gc = min(max(sx0 + lc, 0), W-1);
    size_t ld_off = (size_t)gr * W + gc;

    const float* sp = src + ((size_t)b * CH) * (H*W);
    float* op = out + (size_t)b * CH * plane + (size_t)y*GW + x;

    int i2 = tid + 256;
    int tr0 = tid / HLX, tc0 = tid % HLX;            // tmpH item 0 (tid<352 guard below)
    int tr1 = i2 / HLX,  tc1 = i2 % HLX;
    int hy0 = tid / HLX, hx0 = tid % HLX;            // hrt item 0
    int hy1 = i2 / HLX,  hx1 = i2 % HLX;

    __syncthreads();

    for (int c = 0; c < CH; c++) {
        const float* cp = sp + (size_t)c * (H*W);
        s2t[lr][lc] = __ldg(&cp[ld_off]);
        __syncthreads();

        // horizontal bicubic: 16 rows x 22 cols
        {
            if (tid < SRCT*HLX) {
                tmpH[tr0][tc0] = wxs[tc0][0]*s2t[tr0][cxs[tc0][0]]
                               + wxs[tc0][1]*s2t[tr0][cxs[tc0][1]]
                               + wxs[tc0][2]*s2t[tr0][cxs[tc0][2]]
                               + wxs[tc0][3]*s2t[tr0][cxs[tc0][3]];
            }
            if (i2 < SRCT*HLX) {
                tmpH[tr1][tc1] = wxs[tc1][0]*s2t[tr1][cxs[tc1][0]]
                               + wxs[tc1][1]*s2t[tr1][cxs[tc1][1]]
                               + wxs[tc1][2]*s2t[tr1][cxs[tc1][2]]
                               + wxs[tc1][3]*s2t[tr1][cxs[tc1][3]];
            }
        }
        __syncthreads();

        // vertical bicubic: 22 x 22
        {
            hrt[hy0][hx0] = wys[hy0][0]*tmpH[rys[hy0][0]][hx0]
                          + wys[hy0][1]*tmpH[rys[hy0][1]][hx0]
                          + wys[hy0][2]*tmpH[rys[hy0][2]][hx0]
                          + wys[hy0][3]*tmpH[rys[hy0][3]][hx0];
            if (i2 < HLY*HLX) {
                hrt[hy1][hx1] = wys[hy1][0]*tmpH[rys[hy1][0]][hx1]
                              + wys[hy1][1]*tmpH[rys[hy1][1]][hx1]
                              + wys[hy1][2]*tmpH[rys[hy1][2]][hx1]
                              + wys[hy1][3]*tmpH[rys[hy1][3]][hx1];
            }
        }
        __syncthreads();

        // 7x7 adaptive conv
        float acc = 0.f;
        #pragma unroll
        for (int i = 0; i < DIAM; i++)
            #pragma unroll
            for (int j = 0; j < DIAM; j++)
                acc += w[i*DIAM + j] * hrt[ty+i][tx+j];
        op[(size_t)c * plane] = do_round ? __uint_as_float(f2tf32(acc)) : acc;
        __syncthreads();
    }
}

// ---------------- tf32 tensor-core GEMM with cp.async 3-stage pipeline ----------------
#define GBM 128
#define GBN 128
#define GBK 16
#define GNK (CH/GBK)   // 24
#define NSTG 3

__device__ __forceinline__ void mma_tf32(float c[4],
        uint32_t a0, uint32_t a1, uint32_t a2, uint32_t a3,
        uint32_t b0, uint32_t b1) {
    asm volatile(
        "mma.sync.aligned.m16n8k8.row.col.f32.tf32.tf32.f32 "
        "{%0,%1,%2,%3},{%4,%5,%6,%7},{%8,%9},{%0,%1,%2,%3};\n"
        : "+f"(c[0]), "+f"(c[1]), "+f"(c[2]), "+f"(c[3])
        : "r"(a0), "r"(a1), "r"(a2), "r"(a3), "r"(b0), "r"(b1));
}
#define CP_ASYNC16(dst, src) \
    asm volatile("cp.async.cg.shared.global [%0], [%1], 16;\n" :: "r"(dst), "l"(src))
#define CP_COMMIT() asm volatile("cp.async.commit_group;\n" ::)
#define CP_WAIT1()  asm volatile("cp.async.wait_group 1;\n" ::)

__global__ void __launch_bounds__(256) gemm_tf32_kernel(
        const float* __restrict__ A, const float* __restrict__ Bmat,
        const float* __restrict__ bias, float* __restrict__ C, int N) {
    __shared__ float As[NSTG][GBM][20];
    __shared__ float Bs[NSTG][GBK][136];

    int tid = threadIdx.x;
    int warp = tid / 32, lane = tid % 32;
    int wm = warp / 4, wn = warp % 4;
    int g = lane / 4, tig = lane % 4;
    int bx = blockIdx.x * GBN, by = blockIdx.y * GBM;
    const float* Bb = Bmat + (size_t)blockIdx.z * CH * N;
    float* Cb = C + (size_t)blockIdx.z * OUTC * N;

    float acc[4][4][4];
    #pragma unroll
    for (int mi = 0; mi < 4; mi++)
        #pragma unroll
        for (int ni = 0; ni < 4; ni++)
            #pragma unroll
            for (int q = 0; q < 4; q++) acc[mi][ni][q] = 0.f;

    int ar0 = tid >> 2,        ac0 = (tid & 3) << 2;
    int ar1 = (tid+256) >> 2,  ac1 = ac0;
    int br0 = tid >> 5,        bc0 = (tid & 31) << 2;
    int br1 = (tid+256) >> 5,  bc1 = bc0;

    const float* a0p = &A[(size_t)(by + ar0)*CH + ac0];
    const float* a1p = &A[(size_t)(by + ar1)*CH + ac1];
    const float* b0p = &Bb[(size_t)br0*N + bx + bc0];
    const float* b1p = &Bb[(size_t)br1*N + bx + bc1];

    uint32_t sa0[NSTG], sa1[NSTG], sb0[NSTG], sb1[NSTG];
    #pragma unroll
    for (int s = 0; s < NSTG; s++) {
        sa0[s] = (uint32_t)__cvta_generic_to_shared(&As[s][ar0][ac0]);
        sa1[s] = (uint32_t)__cvta_generic_to_shared(&As[s][ar1][ac1]);
        sb0[s] = (uint32_t)__cvta_generic_to_shared(&Bs[s][br0][bc0]);
        sb1[s] = (uint32_t)__cvta_generic_to_shared(&Bs[s][br1][bc1]);
    }

    // prologue: stages 0 and 1
    #pragma unroll
    for (int s = 0; s < 2; s++) {
        int k0 = s * GBK;
        CP_ASYNC16(sa0[s], a0p + k0);
        CP_ASYNC16(sa1[s], a1p + k0);
        CP_ASYNC16(sb0[s], b0p + (size_t)k0 * N);
        CP_ASYNC16(sb1[s], b1p + (size_t)k0 * N);
        CP_COMMIT();
    }

    for (int kt = 0; kt < GNK; kt++) {
        int cur = kt % NSTG;
        CP_WAIT1();
        __syncthreads();
        if (kt + 2 < GNK) {
            int s = (kt + 2) % NSTG;
            int k0 = (kt + 2) * GBK;
            CP_ASYNC16(sa0[s], a0p + k0);
            CP_ASYNC16(sa1[s], a1p + k0);
            CP_ASYNC16(sb0[s], b0p + (size_t)k0 * N);
            CP_ASYNC16(sb1[s], b1p + (size_t)k0 * N);
        }
        CP_COMMIT();

        #pragma unroll
        for (int ksub = 0; ksub < 2; ksub++) {
            int kb = ksub * 8;
            uint32_t af[4][4], bf[4][2];
            #pragma unroll
            for (int mi = 0; mi < 4; mi++) {
                int row = wm*64 + mi*16 + g;
                af[mi][0] = __float_as_uint(As[cur][row  ][kb + tig]);
                af[mi][1] = __float_as_uint(As[cur][row+8][kb + tig]);
                af[mi][2] = __float_as_uint(As[cur][row  ][kb + tig + 4]);
                af[mi][3] = __float_as_uint(As[cur][row+8][kb + tig + 4]);
            }
            #pragma unroll
            for (int ni = 0; ni < 4; ni++) {
                int col = wn*32 + ni*8 + g;
                bf[ni][0] = __float_as_uint(Bs[cur][kb + tig    ][col]);
                bf[ni][1] = __float_as_uint(Bs[cur][kb + tig + 4][col]);
            }
            #pragma unroll
            for (int mi = 0; mi < 4; mi++)
                #pragma unroll
                for (int ni = 0; ni < 4; ni++)
                    mma_tf32(acc[mi][ni], af[mi][0], af[mi][1], af[mi][2], af[mi][3],
                             bf[ni][0], bf[ni][1]);
        }
    }

    #pragma unroll
    for (int mi = 0; mi < 4; mi++) {
        int r0 = by + wm*64 + mi*16 + g;
        float bi0 = bias[r0], bi1 = bias[r0 + 8];
        #pragma unroll
        for (int ni = 0; ni < 4; ni++) {
            int cc = bx + wn*32 + ni*8 + tig*2;
            *(float2*)&Cb[(size_t)r0*N + cc]     = make_float2(acc[mi][ni][0]+bi0, acc[mi][ni][1]+bi0);
            *(float2*)&Cb[(size_t)(r0+8)*N + cc] = make_float2(acc[mi][ni][2]+bi1, acc[mi][ni][3]+bi1);
        }
    }
}

// ---------------- host launch ----------------
extern "C" void kernel_launch(void* const* d_in, const int* in_sizes, int n_in,
                              void* d_out, int out_size) {
    const float* source   = (const float*)d_in[0];
    const float* guidance = (const float*)d_in[1];
    const float* u1w1 = (const float*)d_in[2];
    const float* u1b1 = (const float*)d_in[3];
    const float* u1w2 = (const float*)d_in[4];
    const float* u1b2 = (const float*)d_in[5];
    const float* u1rt = (const float*)d_in[6];
    const float* u1sg = (const float*)d_in[7];
    const float* u2w1 = (const float*)d_in[8];
    const float* u2b1 = (const float*)d_in[9];
    const float* u2w2 = (const float*)d_in[10];
    const float* u2b2 = (const float*)d_in[11];
    const float* u2rt = (const float*)d_in[12];
    const float* u2sg = (const float*)d_in[13];
    const float* fixw = (const float*)d_in[14];
    const float* fixb = (const float*)d_in[15];
    const float* prjw = (const float*)d_in[16];
    const float* prjb = (const float*)d_in[17];
    float* out = (float*)d_out;

    float *g1, *g2, *p1, *p2, *c1, *c2, *s2, *s4, *weff, *beff;
    cudaGetSymbolAddress((void**)&g1,  g_g1);
    cudaGetSymbolAddress((void**)&g2,  g_g2);
    cudaGetSymbolAddress((void**)&p1,  g_p1);
    cudaGetSymbolAddress((void**)&p2,  g_p2);
    cudaGetSymbolAddress((void**)&c1,  g_c1);
    cudaGetSymbolAddress((void**)&c2,  g_c2);
    cudaGetSymbolAddress((void**)&s2,  g_s2);
    cudaGetSymbolAddress((void**)&s4,  g_s4);
    cudaGetSymbolAddress((void**)&weff, g_weff);
    cudaGetSymbolAddress((void**)&beff, g_beff);

    weff_kernel<<<(OUTC*CH + 255)/256, 256>>>(prjw, prjb, fixw, fixb, weff, beff);

    pool_kernel<<<(BATCH*3*96*96   + 255)/256, 256>>>(guidance, g1, 96, 96, 8);
    pool_kernel<<<(BATCH*3*192*192 + 255)/256, 256>>>(guidance, g2, 192, 192, 4);

    // ---- stage 1: 48 -> 96 ----
    rproj_kernel<<<(BATCH*96*96 + 255)/256, 256>>>(g1, u1w1, u1b1, u1w2, u1b2, p1, 96, 96);
    comb_kernel <<<(BATCH*96*96 + 255)/256, 256>>>(p1, u1rt, u1sg, c1, 96, 96);
    jbu_fused_kernel<<<dim3(96/ATX, 96/ATY, BATCH), 256>>>(source, c1, s2, 48, 48, 0);

    // ---- stage 2: 96 -> 192 (output tf32-rounded for the GEMM) ----
    rproj_kernel<<<(BATCH*192*192 + 255)/256, 256>>>(g2, u2w1, u2b1, u2w2, u2b2, p2, 192, 192);
    comb_kernel <<<(BATCH*192*192 + 255)/256, 256>>>(p2, u2rt, u2sg, c2, 192, 192);
    jbu_fused_kernel<<<dim3(192/ATX, 192/ATY, BATCH), 256>>>(s2, c2, s4, 96, 96, 1);

    // ---- fused fixup+proj GEMM (tf32 tensor cores, cp.async pipeline) ----
    gemm_tf32_kernel<<<dim3(192*192/GBN, OUTC/GBM, BATCH), 256>>>(weff, s4, beff, out, 192*192);
}

// round 4
// speedup vs baseline: 2.3993x; 1.5000x over previous
#include <cuda_runtime.h>
#include <math.h>
#include <stdint.h>

#define BATCH 8
#define CH    384
#define OUTC  256
#define KD    32
#define RAD   3
#define DIAM  7
#define NTAP  49

// ---------------- scratch ----------------
__device__ float g_g1  [BATCH*3*96*96];
__device__ float g_g2  [BATCH*3*192*192];
__device__ float g_p1  [BATCH*KD*96*96];
__device__ float g_p2  [BATCH*KD*192*192];
__device__ float g_c1  [BATCH*NTAP*96*96];
__device__ float g_c2  [BATCH*NTAP*192*192];
__device__ float g_s2  [(size_t)BATCH*CH*96*96];
__device__ float g_s4  [(size_t)BATCH*CH*192*192];
__device__ float g_weff[OUTC*CH];
__device__ float g_beff[OUTC];

__device__ __forceinline__ int refl(int i, int n) {
    if (i < 0) i = -i;
    if (i >= n) i = 2*n - 2 - i;
    return i;
}
__device__ __forceinline__ uint32_t f2tf32(float x) {
    uint32_t u;
    asm("cvt.rna.tf32.f32 %0, %1;" : "=r"(u) : "f"(x));
    return u;
}

// ---------------- W_eff = P + 0.1 P F ; b_eff = pb + 0.1 P fb (tf32-rounded W) ----------------
__global__ void weff_kernel(const float* __restrict__ Pw, const float* __restrict__ pb,
                            const float* __restrict__ Fw, const float* __restrict__ fb,
                            float* __restrict__ Weff, float* __restrict__ beff) {
    int idx = blockIdx.x * blockDim.x + threadIdx.x;
    if (idx < OUTC*CH) {
        int o = idx / CH, c = idx % CH;
        float acc = 0.f;
        #pragma unroll 4
        for (int k = 0; k < CH; k++) acc += Pw[o*CH + k] * Fw[k*CH + c];
        Weff[idx] = __uint_as_float(f2tf32(Pw[o*CH + c] + 0.1f * acc));
    }
    if (idx < OUTC) {
        float a = 0.f;
        for (int k = 0; k < CH; k++) a += Pw[idx*CH + k] * fb[k];
        beff[idx] = pb[idx] + 0.1f * a;
    }
}

// ---------------- adaptive avg pool ----------------
__global__ void pool_kernel(const float* __restrict__ g, float* __restrict__ out,
                            int OH, int OW, int F) {
    int idx = blockIdx.x * blockDim.x + threadIdx.x;
    int total = BATCH * 3 * OH * OW;
    if (idx >= total) return;
    int ox = idx % OW; int t = idx / OW;
    int oy = t % OH;   t /= OH;
    int c  = t % 3;    int b = t / 3;
    const float* p = g + (((size_t)(b*3 + c)*768) + (size_t)oy*F)*768 + (size_t)ox*F;
    float s = 0.f;
    for (int i = 0; i < F; i++)
        for (int j = 0; j < F; j++)
            s += p[i*768 + j];
    out[idx] = s / (float)(F*F);
}

// ---------------- range projection MLP: 3 -> 32 (gelu) -> 32, CHANNEL-major out ----------------
__global__ void rproj_kernel(const float* __restrict__ g,
                             const float* __restrict__ w1, const float* __restrict__ b1,
                             const float* __restrict__ w2, const float* __restrict__ b2,
                             float* __restrict__ proj, int GH, int GW) {
    __shared__ float sw1[KD*3], sb1[KD], sw2[KD*KD], sb2[KD];
    int tid = threadIdx.x;
    for (int i = tid; i < KD*3;  i += blockDim.x) sw1[i] = w1[i];
    for (int i = tid; i < KD;    i += blockDim.x) { sb1[i] = b1[i]; sb2[i] = b2[i]; }
    for (int i = tid; i < KD*KD; i += blockDim.x) sw2[i] = w2[i];
    __syncthreads();
    int idx = blockIdx.x * blockDim.x + tid;
    int plane = GH * GW;
    if (idx >= BATCH * plane) return;
    int b = idx / plane, pix = idx % plane;
    float g0 = g[(size_t)(b*3 + 0)*plane + pix];
    float g1v = g[(size_t)(b*3 + 1)*plane + pix];
    float g2v = g[(size_t)(b*3 + 2)*plane + pix];
    float h[KD];
    #pragma unroll
    for (int o = 0; o < KD; o++) {
        float x = sw1[o*3]*g0 + sw1[o*3+1]*g1v + sw1[o*3+2]*g2v + sb1[o];
        float u = 0.7978845608028654f * (x + 0.044715f * x*x*x);
        h[o] = 0.5f * x * (1.f + tanhf(u));
    }
    float* op = proj + (size_t)b * KD * plane + pix;
    #pragma unroll
    for (int o = 0; o < KD; o++) {
        float s = sb2[o];
        #pragma unroll
        for (int k = 0; k < KD; k++) s += sw2[o*KD + k] * h[k];
        op[(size_t)o * plane] = s;
    }
}

// ---------------- tiled combined-kernel: softmax(range)*spatial, tap-major out ----------------
#define CTX 32
#define CTY 8
#define CHLX 38
#define CHLY 14
#define CITEMS (CHLX*CHLY)   // 532
__global__ void __launch_bounds__(256) comb_tiled_kernel(
        const float* __restrict__ proj,   // [B][KD][plane]
        const float* __restrict__ rt_p, const float* __restrict__ sig_p,
        float* __restrict__ comb,          // [B][NTAP][plane]
        int GH, int GW) {
    __shared__ float tile[2][CHLY][40];
    __shared__ int soff[CITEMS];
    int tid = threadIdx.x;
    int tx = tid % 32, ty = tid / 32;
    int x0 = blockIdx.x * CTX, y0 = blockIdx.y * CTY;
    int b = blockIdx.z;
    int x = x0 + tx, y = y0 + ty;
    int plane = GH * GW;

    for (int i = tid; i < CITEMS; i += 256) {
        int hy = i / CHLX, hx = i % CHLX;
        soff[i] = refl(y0 + hy - RAD, GH)*GW + refl(x0 + hx - RAD, GW);
    }
    __syncthreads();
    int so0 = soff[tid];
    int so1 = soff[tid + 256];
    int so2 = (tid < CITEMS - 512) ? soff[tid + 512] : 0;
    int r0 = tid / CHLX,        c0 = tid % CHLX;
    int r1 = (tid+256) / CHLX,  c1 = (tid+256) % CHLX;
    int r2 = (tid+512) / CHLX,  c2 = (tid+512) % CHLX;

    const float* pb_ = proj + (size_t)b * KD * plane;
    // k = 0 direct
    {
        const float* kp = pb_;
        tile[0][r0][c0] = __ldg(&kp[so0]);
        tile[0][r1][c1] = __ldg(&kp[so1]);
        if (tid < CITEMS - 512) tile[0][r2][c2] = __ldg(&kp[so2]);
    }
    __syncthreads();

    float l[NTAP];
    #pragma unroll
    for (int p = 0; p < NTAP; p++) l[p] = 0.f;

    for (int k = 0; k < KD; k++) {
        int cur = k & 1;
        float pf0 = 0.f, pf1 = 0.f, pf2 = 0.f;
        if (k + 1 < KD) {
            const float* kp = pb_ + (size_t)(k+1) * plane;
            pf0 = __ldg(&kp[so0]);
            pf1 = __ldg(&kp[so1]);
            if (tid < CITEMS - 512) pf2 = __ldg(&kp[so2]);
        }
        float cv = tile[cur][ty+RAD][tx+RAD];
        #pragma unroll
        for (int i = 0; i < DIAM; i++)
            #pragma unroll
            for (int j = 0; j < DIAM; j++)
                l[i*DIAM+j] += cv * tile[cur][ty+i][tx+j];
        if (k + 1 < KD) {
            tile[cur^1][r0][c0] = pf0;
            tile[cur^1][r1][c1] = pf1;
            if (tid < CITEMS - 512) tile[cur^1][r2][c2] = pf2;
        }
        __syncthreads();
    }

    float temp = expf(rt_p[0]);
    temp = fminf(fmaxf(temp, 1e-4f), 1e4f);
    float sig = sig_p[0];
    float inv2s2 = 1.f / (2.f * sig * sig);

    float m = -1e30f;
    #pragma unroll
    for (int p = 0; p < NTAP; p++) { l[p] *= temp; m = fmaxf(m, l[p]); }
    float Z = 0.f;
    #pragma unroll
    for (int p = 0; p < NTAP; p++) { l[p] = expf(l[p] - m); Z += l[p]; }
    float invZ = 1.f / Z;
    float S = 0.f;
    #pragma unroll
    for (int p = 0; p < NTAP; p++) {
        int i = p / DIAM, j = p % DIAM;
        float dy = (i - 3) * (1.f/3.f), dx = (j - 3) * (1.f/3.f);
        float sp = expf(-(dx*dx + dy*dy) * inv2s2);
        l[p] = (l[p] * invZ) * sp;
        S += l[p];
    }
    S = fmaxf(S, 1e-7f);
    float invS = 1.f / S;
    float* op = comb + (size_t)b * NTAP * plane + (size_t)y*GW + x;
    #pragma unroll
    for (int p = 0; p < NTAP; p++) op[(size_t)p * plane] = l[p] * invS;
}

// ---------------- bicubic weight helper ----------------
__device__ __forceinline__ float keysw(float x) {
    x = fabsf(x);
    if (x <= 1.f)      return ((1.5f*x - 2.5f)*x)*x + 1.f;
    else if (x < 2.f)  return ((-0.5f*x + 2.5f)*x - 4.f)*x + 2.f;
    return 0.f;
}
__device__ __forceinline__ void cubw(int o, int n, int* base, float w[4]) {
    float cc = 0.5f * o - 0.25f;
    int bb = (int)floorf(cc);
    float t = cc - (float)bb;
    w[0] = keysw(1.f + t); w[1] = keysw(t); w[2] = keysw(1.f - t); w[3] = keysw(2.f - t);
    float s = 0.f;
    #pragma unroll
    for (int k = 0; k < 4; k++) {
        int ii = bb - 1 + k;
        if (ii < 0 || ii >= n) w[k] = 0.f;
        s += w[k];
    }
    float inv = 1.f / s;
    #pragma unroll
    for (int k = 0; k < 4; k++) w[k] *= inv;
    *base = bb - 1;
}

// ---------------- FUSED bicubic 2x + adaptive 7x7 conv (32x8 tile, 2 ch/iter) ----------------
#define TLX 32
#define TLY 8
#define HLX 38
#define HLY 14
#define SRCW 24
#define SRCH 12
#define NHIT (HLX*SRCH)      // 456  tmpH items per channel
#define NVIT (HLX*HLY)       // 532  hrt items per channel
#define NSIT (SRCW*SRCH)     // 288  src items per channel
__global__ void __launch_bounds__(256) jbu_fused_kernel(
        const float* __restrict__ src, const float* __restrict__ comb,
        float* __restrict__ out, int H, int W, int do_round) {
    int GH = 2*H, GW = 2*W;
    __shared__ float s2t[2][SRCH][25];
    __shared__ float tmpH[2][SRCH][40];
    __shared__ float hrt[2][HLY][40];
    __shared__ float wxs[HLX][4]; __shared__ int cxs[HLX][4];
    __shared__ float wys[HLY][4]; __shared__ int rys[HLY][4];

    int tid = threadIdx.x;
    int tx = tid % 32, ty = tid / 32;
    int x0 = blockIdx.x * TLX, y0 = blockIdx.y * TLY;
    int b = blockIdx.z;
    int x = x0 + tx, y = y0 + ty;
    int plane = GH * GW;
    int sx0 = x0/2 - 4, sy0 = y0/2 - 4;

    if (tid < HLX + HLY) {
        if (tid < HLX) {
            int l = tid;
            int gx = refl(x0 - RAD + l, GW);
            int base; float w[4]; cubw(gx, W, &base, w);
            #pragma unroll
            for (int k = 0; k < 4; k++) {
                cxs[l][k] = min(max(base + k, 0), W-1) - sx0;
                wxs[l][k] = w[k];
            }
        } else {
            int l = tid - HLX;
            int gy = refl(y0 - RAD + l, GH);
            int base; float w[4]; cubw(gy, H, &base, w);
            #pragma unroll
            for (int k = 0; k < 4; k++) {
                rys[l][k] = min(max(base + k, 0), H-1) - sy0;
                wys[l][k] = w[k];
            }
        }
    }

    // per-pixel conv weights (tap-major comb: coalesced)
    float w[NTAP];
    {
        const float* wp = comb + (size_t)b * NTAP * plane + (size_t)y*GW + x;
        #pragma unroll
        for (int p = 0; p < NTAP; p++) w[p] = __ldg(&wp[(size_t)p * plane]);
    }

    // src staging offsets (clamped), up to 2 items/thread
    int sr0 = tid / SRCW,        sc0 = tid % SRCW;
    int sr1 = (tid+256) / SRCW,  sc1 = (tid+256) % SRCW;
    int has1 = (tid + 256 < NSIT);
    size_t o0 = (size_t)min(max(sy0 + sr0, 0), H-1)*W + min(max(sx0 + sc0, 0), W-1);
    size_t o1 = (size_t)min(max(sy0 + sr1, 0), H-1)*W + min(max(sx0 + sc1, 0), W-1);

    const float* sp = src + ((size_t)b * CH) * (H*W);
    float* op = out + (size_t)b * CH * plane + (size_t)y*GW + x;

    __syncthreads();

    // prologue: channels 0,1
    {
        const float* c0p = sp;
        const float* c1p = sp + (size_t)(H*W);
        s2t[0][sr0][sc0] = __ldg(&c0p[o0]);
        s2t[1][sr0][sc0] = __ldg(&c1p[o0]);
        if (has1) {
            s2t[0][sr1][sc1] = __ldg(&c0p[o1]);
            s2t[1][sr1][sc1] = __ldg(&c1p[o1]);
        }
    }
    __syncthreads();

    for (int it = 0; it < CH/2; it++) {
        int c = 2*it;
        // prefetch channels c+2, c+3
        float pf[2][2];
        int havepf = (it + 1 < CH/2);
        if (havepf) {
            const float* c2p = sp + (size_t)(c+2)*(H*W);
            const float* c3p = sp + (size_t)(c+3)*(H*W);
            pf[0][0] = __ldg(&c2p[o0]);
            pf[1][0] = __ldg(&c3p[o0]);
            if (has1) { pf[0][1] = __ldg(&c2p[o1]); pf[1][1] = __ldg(&c3p[o1]); }
        }

        // H pass: 2 x 456 items
        #pragma unroll
        for (int q = 0; q < 4; q++) {
            int i = tid + q*256;
            if (i < 2*NHIT) {
                int ch = i / NHIT, rem = i % NHIT;
                int r = rem / HLX, hc = rem % HLX;
                tmpH[ch][r][hc] = wxs[hc][0]*s2t[ch][r][cxs[hc][0]]
                                + wxs[hc][1]*s2t[ch][r][cxs[hc][1]]
                                + wxs[hc][2]*s2t[ch][r][cxs[hc][2]]
                                + wxs[hc][3]*s2t[ch][r][cxs[hc][3]];
            }
        }
        __syncthreads();

        // store prefetch into s2t (s2t fully consumed by H pass)
        if (havepf) {
            s2t[0][sr0][sc0] = pf[0][0];
            s2t[1][sr0][sc0] = pf[1][0];
            if (has1) { s2t[0][sr1][sc1] = pf[0][1]; s2t[1][sr1][sc1] = pf[1][1]; }
        }

        // V pass: 2 x 532 items
        #pragma unroll
        for (int q = 0; q < 5; q++) {
            int i = tid + q*256;
            if (i < 2*NVIT) {
                int ch = i / NVIT, rem = i % NVIT;
                int hy = rem / HLX, hx = rem % HLX;
                hrt[ch][hy][hx] = wys[hy][0]*tmpH[ch][rys[hy][0]][hx]
                                + wys[hy][1]*tmpH[ch][rys[hy][1]][hx]
                                + wys[hy][2]*tmpH[ch][rys[hy][2]][hx]
                                + wys[hy][3]*tmpH[ch][rys[hy][3]][hx];
            }
        }
        __syncthreads();

        // 7x7 adaptive conv, both channels
        #pragma unroll
        for (int ch = 0; ch < 2; ch++) {
            float acc = 0.f;
            #pragma unroll
            for (int i = 0; i < DIAM; i++)
                #pragma unroll
                for (int j = 0; j < DIAM; j++)
                    acc += w[i*DIAM + j] * hrt[ch][ty+i][tx+j];
            op[(size_t)(c+ch) * plane] = do_round ? __uint_as_float(f2tf32(acc)) : acc;
        }
        __syncthreads();
    }
}

// ---------------- tf32 tensor-core GEMM with cp.async 3-stage pipeline ----------------
#define GBM 128
#define GBN 128
#define GBK 16
#define GNK (CH/GBK)   // 24
#define NSTG 3

__device__ __forceinline__ void mma_tf32(float c[4],
        uint32_t a0, uint32_t a1, uint32_t a2, uint32_t a3,
        uint32_t b0, uint32_t b1) {
    asm volatile(
        "mma.sync.aligned.m16n8k8.row.col.f32.tf32.tf32.f32 "
        "{%0,%1,%2,%3},{%4,%5,%6,%7},{%8,%9},{%0,%1,%2,%3};\n"
        : "+f"(c[0]), "+f"(c[1]), "+f"(c[2]), "+f"(c[3])
        : "r"(a0), "r"(a1), "r"(a2), "r"(a3), "r"(b0), "r"(b1));
}
#define CP_ASYNC16(dst, src) \
    asm volatile("cp.async.cg.shared.global [%0], [%1], 16;\n" :: "r"(dst), "l"(src))
#define CP_COMMIT() asm volatile("cp.async.commit_group;\n" ::)
#define CP_WAIT1()  asm volatile("cp.async.wait_group 1;\n" ::)

__global__ void __launch_bounds__(256) gemm_tf32_kernel(
        const float* __restrict__ A, const float* __restrict__ Bmat,
        const float* __restrict__ bias, float* __restrict__ C, int N) {
    __shared__ float As[NSTG][GBM][20];
    __shared__ float Bs[NSTG][GBK][136];

    int tid = threadIdx.x;
    int warp = tid / 32, lane = tid % 32;
    int wm = warp / 4, wn = warp % 4;
    int g = lane / 4, tig = lane % 4;
    int bx = blockIdx.x * GBN, by = blockIdx.y * GBM;
    const float* Bb = Bmat + (size_t)blockIdx.z * CH * N;
    float* Cb = C + (size_t)blockIdx.z * OUTC * N;

    float acc[4][4][4];
    #pragma unroll
    for (int mi = 0; mi < 4; mi++)
        #pragma unroll
        for (int ni = 0; ni < 4; ni++)
            #pragma unroll
            for (int q = 0; q < 4; q++) acc[mi][ni][q] = 0.f;

    int ar0 = tid >> 2,        ac0 = (tid & 3) << 2;
    int ar1 = (tid+256) >> 2,  ac1 = ac0;
    int br0 = tid >> 5,        bc0 = (tid & 31) << 2;
    int br1 = (tid+256) >> 5,  bc1 = bc0;

    const float* a0p = &A[(size_t)(by + ar0)*CH + ac0];
    const float* a1p = &A[(size_t)(by + ar1)*CH + ac1];
    const float* b0p = &Bb[(size_t)br0*N + bx + bc0];
    const float* b1p = &Bb[(size_t)br1*N + bx + bc1];

    uint32_t sa0[NSTG], sa1[NSTG], sb0[NSTG], sb1[NSTG];
    #pragma unroll
    for (int s = 0; s < NSTG; s++) {
        sa0[s] = (uint32_t)__cvta_generic_to_shared(&As[s][ar0][ac0]);
        sa1[s] = (uint32_t)__cvta_generic_to_shared(&As[s][ar1][ac1]);
        sb0[s] = (uint32_t)__cvta_generic_to_shared(&Bs[s][br0][bc0]);
        sb1[s] = (uint32_t)__cvta_generic_to_shared(&Bs[s][br1][bc1]);
    }

    #pragma unroll
    for (int s = 0; s < 2; s++) {
        int k0 = s * GBK;
        CP_ASYNC16(sa0[s], a0p + k0);
        CP_ASYNC16(sa1[s], a1p + k0);
        CP_ASYNC16(sb0[s], b0p + (size_t)k0 * N);
        CP_ASYNC16(sb1[s], b1p + (size_t)k0 * N);
        CP_COMMIT();
    }

    for (int kt = 0; kt < GNK; kt++) {
        int cur = kt % NSTG;
        CP_WAIT1();
        __syncthreads();
        if (kt + 2 < GNK) {
            int s = (kt + 2) % NSTG;
            int k0 = (kt + 2) * GBK;
            CP_ASYNC16(sa0[s], a0p + k0);
            CP_ASYNC16(sa1[s], a1p + k0);
            CP_ASYNC16(sb0[s], b0p + (size_t)k0 * N);
            CP_ASYNC16(sb1[s], b1p + (size_t)k0 * N);
        }
        CP_COMMIT();

        #pragma unroll
        for (int ksub = 0; ksub < 2; ksub++) {
            int kb = ksub * 8;
            uint32_t af[4][4], bf[4][2];
            #pragma unroll
            for (int mi = 0; mi < 4; mi++) {
                int row = wm*64 + mi*16 + g;
                af[mi][0] = __float_as_uint(As[cur][row  ][kb + tig]);
                af[mi][1] = __float_as_uint(As[cur][row+8][kb + tig]);
                af[mi][2] = __float_as_uint(As[cur][row  ][kb + tig + 4]);
                af[mi][3] = __float_as_uint(As[cur][row+8][kb + tig + 4]);
            }
            #pragma unroll
            for (int ni = 0; ni < 4; ni++) {
                int col = wn*32 + ni*8 + g;
                bf[ni][0] = __float_as_uint(Bs[cur][kb + tig    ][col]);
                bf[ni][1] = __float_as_uint(Bs[cur][kb + tig + 4][col]);
            }
            #pragma unroll
            for (int mi = 0; mi < 4; mi++)
                #pragma unroll
                for (int ni = 0; ni < 4; ni++)
                    mma_tf32(acc[mi][ni], af[mi][0], af[mi][1], af[mi][2], af[mi][3],
                             bf[ni][0], bf[ni][1]);
        }
    }

    #pragma unroll
    for (int mi = 0; mi < 4; mi++) {
        int r0 = by + wm*64 + mi*16 + g;
        float bi0 = bias[r0], bi1 = bias[r0 + 8];
        #pragma unroll
        for (int ni = 0; ni < 4; ni++) {
            int cc = bx + wn*32 + ni*8 + tig*2;
            *(float2*)&Cb[(size_t)r0*N + cc]     = make_float2(acc[mi][ni][0]+bi0, acc[mi][ni][1]+bi0);
            *(float2*)&Cb[(size_t)(r0+8)*N + cc] = make_float2(acc[mi][ni][2]+bi1, acc[mi][ni][3]+bi1);
        }
    }
}

// ---------------- host launch ----------------
extern "C" void kernel_launch(void* const* d_in, const int* in_sizes, int n_in,
                              void* d_out, int out_size) {
    const float* source   = (const float*)d_in[0];
    const float* guidance = (const float*)d_in[1];
    const float* u1w1 = (const float*)d_in[2];
    const float* u1b1 = (const float*)d_in[3];
    const float* u1w2 = (const float*)d_in[4];
    const float* u1b2 = (const float*)d_in[5];
    const float* u1rt = (const float*)d_in[6];
    const float* u1sg = (const float*)d_in[7];
    const float* u2w1 = (const float*)d_in[8];
    const float* u2b1 = (const float*)d_in[9];
    const float* u2w2 = (const float*)d_in[10];
    const float* u2b2 = (const float*)d_in[11];
    const float* u2rt = (const float*)d_in[12];
    const float* u2sg = (const float*)d_in[13];
    const float* fixw = (const float*)d_in[14];
    const float* fixb = (const float*)d_in[15];
    const float* prjw = (const float*)d_in[16];
    const float* prjb = (const float*)d_in[17];
    float* out = (float*)d_out;

    float *g1, *g2, *p1, *p2, *c1, *c2, *s2, *s4, *weff, *beff;
    cudaGetSymbolAddress((void**)&g1,  g_g1);
    cudaGetSymbolAddress((void**)&g2,  g_g2);
    cudaGetSymbolAddress((void**)&p1,  g_p1);
    cudaGetSymbolAddress((void**)&p2,  g_p2);
    cudaGetSymbolAddress((void**)&c1,  g_c1);
    cudaGetSymbolAddress((void**)&c2,  g_c2);
    cudaGetSymbolAddress((void**)&s2,  g_s2);
    cudaGetSymbolAddress((void**)&s4,  g_s4);
    cudaGetSymbolAddress((void**)&weff, g_weff);
    cudaGetSymbolAddress((void**)&beff, g_beff);

    weff_kernel<<<(OUTC*CH + 255)/256, 256>>>(prjw, prjb, fixw, fixb, weff, beff);

    pool_kernel<<<(BATCH*3*96*96   + 255)/256, 256>>>(guidance, g1, 96, 96, 8);
    pool_kernel<<<(BATCH*3*192*192 + 255)/256, 256>>>(guidance, g2, 192, 192, 4);

    // ---- stage 1: 48 -> 96 ----
    rproj_kernel<<<(BATCH*96*96 + 255)/256, 256>>>(g1, u1w1, u1b1, u1w2, u1b2, p1, 96, 96);
    comb_tiled_kernel<<<dim3(96/CTX, 96/CTY, BATCH), 256>>>(p1, u1rt, u1sg, c1, 96, 96);
    jbu_fused_kernel<<<dim3(96/TLX, 96/TLY, BATCH), 256>>>(source, c1, s2, 48, 48, 0);

    // ---- stage 2: 96 -> 192 ----
    rproj_kernel<<<(BATCH*192*192 + 255)/256, 256>>>(g2, u2w1, u2b1, u2w2, u2b2, p2, 192, 192);
    comb_tiled_kernel<<<dim3(192/CTX, 192/CTY, BATCH), 256>>>(p2, u2rt, u2sg, c2, 192, 192);
    jbu_fused_kernel<<<dim3(192/TLX, 192/TLY, BATCH), 256>>>(s2, c2, s4, 96, 96, 1);

    // ---- fused fixup+proj GEMM ----
    gemm_tf32_kernel<<<dim3(192*192/GBN, OUTC/GBM, BATCH), 256>>>(weff, s4, beff, out, 192*192);
}